// round 1
// baseline (speedup 1.0000x reference)
#include <cuda_runtime.h>
#include <math.h>

// ---------------- problem constants ----------------
#define SEQ     2048
#define HID     4096
#define NH      32
#define NKV     8
#define HD      128
#define KVD     (NKV*HD)     // 1024
#define GROUPS  (NH/NKV)     // 4

// ---------------- scratch (static device globals; no allocation) ----------------
__device__ float g_Q[SEQ * HID];    // 32 MB
__device__ float g_K[SEQ * KVD];    // 8 MB
__device__ float g_V[SEQ * KVD];    // 8 MB
__device__ float g_AO[SEQ * HID];   // 32 MB (attention output, pre-Wo)

// ============================================================================
// Tiled NT GEMM: C[M,N] = A[M,K] * B[N,K]^T   (A,B,C row-major)
// BM=BN=64, BK=16, 256 threads, 4x4 per thread.
// ============================================================================
__global__ void __launch_bounds__(256) gemm_nt_kernel(
    const float* __restrict__ A, const float* __restrict__ B,
    float* __restrict__ C, int M, int N, int K)
{
    __shared__ float As[16][68];   // [k][m], padded to reduce store conflicts
    __shared__ float Bs[16][68];   // [k][n]

    const int tid = threadIdx.x;
    const int tx = tid & 15;         // 0..15 -> n
    const int ty = tid >> 4;         // 0..15 -> m
    const int bm = blockIdx.y * 64;
    const int bn = blockIdx.x * 64;

    const int lrow = tid >> 2;            // 0..63
    const int lk4  = (tid & 3) << 2;      // 0,4,8,12

    const float* Aptr = A + (size_t)(bm + lrow) * K + lk4;
    const float* Bptr = B + (size_t)(bn + lrow) * K + lk4;

    float acc[4][4];
#pragma unroll
    for (int i = 0; i < 4; i++)
#pragma unroll
        for (int j = 0; j < 4; j++) acc[i][j] = 0.f;

    for (int k0 = 0; k0 < K; k0 += 16) {
        float4 a4 = *(const float4*)(Aptr + k0);
        float4 b4 = *(const float4*)(Bptr + k0);
        As[lk4 + 0][lrow] = a4.x; As[lk4 + 1][lrow] = a4.y;
        As[lk4 + 2][lrow] = a4.z; As[lk4 + 3][lrow] = a4.w;
        Bs[lk4 + 0][lrow] = b4.x; Bs[lk4 + 1][lrow] = b4.y;
        Bs[lk4 + 2][lrow] = b4.z; Bs[lk4 + 3][lrow] = b4.w;
        __syncthreads();

#pragma unroll
        for (int kk = 0; kk < 16; kk++) {
            float4 av = *(const float4*)&As[kk][ty * 4];
            float4 bv = *(const float4*)&Bs[kk][tx * 4];
            acc[0][0] += av.x * bv.x; acc[0][1] += av.x * bv.y;
            acc[0][2] += av.x * bv.z; acc[0][3] += av.x * bv.w;
            acc[1][0] += av.y * bv.x; acc[1][1] += av.y * bv.y;
            acc[1][2] += av.y * bv.z; acc[1][3] += av.y * bv.w;
            acc[2][0] += av.z * bv.x; acc[2][1] += av.z * bv.y;
            acc[2][2] += av.z * bv.z; acc[2][3] += av.z * bv.w;
            acc[3][0] += av.w * bv.x; acc[3][1] += av.w * bv.y;
            acc[3][2] += av.w * bv.z; acc[3][3] += av.w * bv.w;
        }
        __syncthreads();
    }

#pragma unroll
    for (int i = 0; i < 4; i++) {
        float* Crow = C + (size_t)(bm + ty * 4 + i) * N + bn + tx * 4;
        float4 v = make_float4(acc[i][0], acc[i][1], acc[i][2], acc[i][3]);
        *(float4*)Crow = v;
    }
}

// ============================================================================
// RoPE in place on Q ([SEQ,HID] as 32 heads x 128) and K ([SEQ,KVD] as 8 x 128)
// pair index i in [0,64): out[i]   = x[i]*cos - x[i+64]*sin
//                         out[i+64]= x[i+64]*cos + x[i]*sin
// ============================================================================
#define NQ_PAIRS (SEQ * NH * 64)    // 4194304
#define NK_PAIRS (SEQ * NKV * 64)   // 1048576

__global__ void __launch_bounds__(256) rope_kernel(float* __restrict__ Q, float* __restrict__ K)
{
    int idx = blockIdx.x * blockDim.x + threadIdx.x;
    float* base;
    int s, i;
    if (idx < NQ_PAIRS) {
        s = idx >> 11;                 // / 2048 pairs per row
        int p = idx & 2047;
        int h = p >> 6;
        i = p & 63;
        base = Q + (size_t)s * HID + h * HD;
    } else {
        int t = idx - NQ_PAIRS;
        if (t >= NK_PAIRS) return;
        s = t >> 9;                    // / 512 pairs per row
        int p = t & 511;
        int h = p >> 6;
        i = p & 63;
        base = K + (size_t)s * KVD + h * HD;
    }
    // inv_freq = theta^(-i/64), computed in double for accuracy
    double invf_d = exp(-(double)i * (13.122363377404328 / 64.0)); // ln(500000)
    float freq = (float)s * (float)invf_d;
    float c = cosf(freq);
    float sn = sinf(freq);
    float x1 = base[i];
    float x2 = base[i + 64];
    base[i]      = x1 * c - x2 * sn;
    base[i + 64] = x2 * c + x1 * sn;
}

// ============================================================================
// Flash attention, fp32, causal. One block per (q-tile of 64, head).
// 256 threads. Dynamic smem.
//   sQ,sK,sV: [64][132] padded rows
//   sS:       [64][65]
// Each thread: S fragment 4x4 (ty,tx in 16x16), O fragment 4 rows x 8 cols.
// ============================================================================
#define QSTR 132
#define SSTR 65
#define ATTN_SMEM_FLOATS (3*64*QSTR + 64*SSTR + 64*3 + 256)
#define ATTN_SMEM_BYTES  (ATTN_SMEM_FLOATS * 4)

extern __shared__ float sm_attn[];

__global__ void __launch_bounds__(256) attn_kernel(
    const float* __restrict__ Q, const float* __restrict__ K,
    const float* __restrict__ V, float* __restrict__ O)
{
    float* sQ = sm_attn;                 // 64*132
    float* sK = sQ + 64 * QSTR;
    float* sV = sK + 64 * QSTR;
    float* sS = sV + 64 * QSTR;          // 64*65
    float* sM = sS + 64 * SSTR;          // 64
    float* sL = sM + 64;                 // 64
    float* sA = sL + 64;                 // 64 (alpha)
    float* sR = sA + 64;                 // 256 (reduction scratch)

    const int tid = threadIdx.x;
    const int qt = blockIdx.x;           // q tile (0..31)
    const int h  = blockIdx.y;           // head (0..31)
    const int hk = h >> 2;               // kv head

    const int ty = tid >> 4, tx = tid & 15;
    const int ry = ty * 4;               // this thread's 4 S/O rows
    const int cx4 = tx * 4;              // 4 S cols
    const int cx8 = tx * 8;              // 8 O cols

    // load Q tile (64 x 128)
    for (int v = tid; v < 64 * 32; v += 256) {
        int row = v >> 5, c4 = (v & 31) << 2;
        *(float4*)&sQ[row * QSTR + c4] =
            *(const float4*)&Q[(size_t)(qt * 64 + row) * HID + h * HD + c4];
    }
    if (tid < 64) { sM[tid] = -1e30f; sL[tid] = 0.f; }

    float acc[4][8];
#pragma unroll
    for (int i = 0; i < 4; i++)
#pragma unroll
        for (int j = 0; j < 8; j++) acc[i][j] = 0.f;

    __syncthreads();

    const float scale = 0.08838834764831845f; // 1/sqrt(128)
    const int r  = tid & 63;             // softmax row owned in reduction phase
    const int qd = tid >> 6;             // quarter (0..3)

    for (int kt = 0; kt <= qt; kt++) {
        // ---- load K,V tiles ----
        for (int v = tid; v < 64 * 32; v += 256) {
            int row = v >> 5, c4 = (v & 31) << 2;
            size_t gb = (size_t)(kt * 64 + row) * KVD + hk * HD + c4;
            *(float4*)&sK[row * QSTR + c4] = *(const float4*)&K[gb];
            *(float4*)&sV[row * QSTR + c4] = *(const float4*)&V[gb];
        }
        __syncthreads();

        // ---- S = Q K^T (4x4 fragment) ----
        float s[4][4];
#pragma unroll
        for (int i = 0; i < 4; i++)
#pragma unroll
            for (int j = 0; j < 4; j++) s[i][j] = 0.f;

        for (int d4 = 0; d4 < 128; d4 += 4) {
            float4 q0 = *(const float4*)&sQ[(ry + 0) * QSTR + d4];
            float4 q1 = *(const float4*)&sQ[(ry + 1) * QSTR + d4];
            float4 q2 = *(const float4*)&sQ[(ry + 2) * QSTR + d4];
            float4 q3 = *(const float4*)&sQ[(ry + 3) * QSTR + d4];
            float4 k0 = *(const float4*)&sK[(cx4 + 0) * QSTR + d4];
            float4 k1 = *(const float4*)&sK[(cx4 + 1) * QSTR + d4];
            float4 k2 = *(const float4*)&sK[(cx4 + 2) * QSTR + d4];
            float4 k3 = *(const float4*)&sK[(cx4 + 3) * QSTR + d4];
#define DOT4(a,b) (a.x*b.x + a.y*b.y + a.z*b.z + a.w*b.w)
            s[0][0] += DOT4(q0,k0); s[0][1] += DOT4(q0,k1); s[0][2] += DOT4(q0,k2); s[0][3] += DOT4(q0,k3);
            s[1][0] += DOT4(q1,k0); s[1][1] += DOT4(q1,k1); s[1][2] += DOT4(q1,k2); s[1][3] += DOT4(q1,k3);
            s[2][0] += DOT4(q2,k0); s[2][1] += DOT4(q2,k1); s[2][2] += DOT4(q2,k2); s[2][3] += DOT4(q2,k3);
            s[3][0] += DOT4(q3,k0); s[3][1] += DOT4(q3,k1); s[3][2] += DOT4(q3,k2); s[3][3] += DOT4(q3,k3);
#undef DOT4
        }

        // ---- scale + causal mask, write to sS ----
        const bool diag = (kt == qt);
#pragma unroll
        for (int i = 0; i < 4; i++) {
            int gq = qt * 64 + ry + i;
#pragma unroll
            for (int j = 0; j < 4; j++) {
                float val = s[i][j] * scale;
                if (diag && (kt * 64 + cx4 + j > gq)) val = -1e30f;
                sS[(ry + i) * SSTR + cx4 + j] = val;
            }
        }
        __syncthreads();

        // ---- row max (partial, 4 threads per row) ----
        {
            float mx = -1e30f;
            const float* rowp = &sS[r * SSTR + qd * 16];
#pragma unroll
            for (int j = 0; j < 16; j++) mx = fmaxf(mx, rowp[j]);
            sR[qd * 64 + r] = mx;
        }
        __syncthreads();
        if (tid < 64) {
            float mold = sM[tid];
            float mnew = fmaxf(fmaxf(sR[tid], sR[64 + tid]),
                               fmaxf(sR[128 + tid], sR[192 + tid]));
            mnew = fmaxf(mold, mnew);
            sM[tid] = mnew;
            sA[tid] = expf(mold - mnew);
        }
        __syncthreads();

        // ---- exp + partial row sums; rescale O accumulators ----
        {
            float mnew = sM[r];
            float psum = 0.f;
            float* rowp = &sS[r * SSTR + qd * 16];
#pragma unroll
            for (int j = 0; j < 16; j++) {
                float p = expf(rowp[j] - mnew);
                rowp[j] = p;
                psum += p;
            }
            sR[qd * 64 + r] = psum;
        }
#pragma unroll
        for (int i = 0; i < 4; i++) {
            float al = sA[ry + i];
#pragma unroll
            for (int j = 0; j < 8; j++) acc[i][j] *= al;
        }
        __syncthreads();
        if (tid < 64) {
            sL[tid] = sL[tid] * sA[tid] +
                      (sR[tid] + sR[64 + tid]) + (sR[128 + tid] + sR[192 + tid]);
        }

        // ---- O += P V ----
        for (int kk = 0; kk < 64; kk++) {
            float4 va = *(const float4*)&sV[kk * QSTR + cx8];
            float4 vb = *(const float4*)&sV[kk * QSTR + cx8 + 4];
#pragma unroll
            for (int i = 0; i < 4; i++) {
                float p = sS[(ry + i) * SSTR + kk];
                acc[i][0] += p * va.x; acc[i][1] += p * va.y;
                acc[i][2] += p * va.z; acc[i][3] += p * va.w;
                acc[i][4] += p * vb.x; acc[i][5] += p * vb.y;
                acc[i][6] += p * vb.z; acc[i][7] += p * vb.w;
            }
        }
        __syncthreads();
    }

    // ---- finalize: O / l, write to g_AO in [s, h*128+d] layout ----
#pragma unroll
    for (int i = 0; i < 4; i++) {
        float inv = 1.0f / sL[ry + i];
        size_t gb = (size_t)(qt * 64 + ry + i) * HID + h * HD + cx8;
        float4 oa = make_float4(acc[i][0] * inv, acc[i][1] * inv,
                                acc[i][2] * inv, acc[i][3] * inv);
        float4 ob = make_float4(acc[i][4] * inv, acc[i][5] * inv,
                                acc[i][6] * inv, acc[i][7] * inv);
        *(float4*)&O[gb] = oa;
        *(float4*)&O[gb + 4] = ob;
    }
}

// ============================================================================
// launch
// ============================================================================
extern "C" void kernel_launch(void* const* d_in, const int* in_sizes, int n_in,
                              void* d_out, int out_size)
{
    const float* X  = (const float*)d_in[0];
    const float* Wq = (const float*)d_in[1];
    const float* Wk = (const float*)d_in[2];
    const float* Wv = (const float*)d_in[3];
    const float* Wo = (const float*)d_in[4];
    float* out = (float*)d_out;

    float *Qp, *Kp, *Vp, *AOp;
    cudaGetSymbolAddress((void**)&Qp,  g_Q);
    cudaGetSymbolAddress((void**)&Kp,  g_K);
    cudaGetSymbolAddress((void**)&Vp,  g_V);
    cudaGetSymbolAddress((void**)&AOp, g_AO);

    cudaFuncSetAttribute(attn_kernel,
                         cudaFuncAttributeMaxDynamicSharedMemorySize,
                         ATTN_SMEM_BYTES);

    // QKV projections
    gemm_nt_kernel<<<dim3(HID / 64, SEQ / 64), 256>>>(X, Wq, Qp, SEQ, HID, HID);
    gemm_nt_kernel<<<dim3(KVD / 64, SEQ / 64), 256>>>(X, Wk, Kp, SEQ, KVD, HID);
    gemm_nt_kernel<<<dim3(KVD / 64, SEQ / 64), 256>>>(X, Wv, Vp, SEQ, KVD, HID);

    // RoPE on Q and K
    {
        int total = NQ_PAIRS + NK_PAIRS;
        rope_kernel<<<(total + 255) / 256, 256>>>(Qp, Kp);
    }

    // attention
    attn_kernel<<<dim3(SEQ / 64, NH), 256, ATTN_SMEM_BYTES>>>(Qp, Kp, Vp, AOp);

    // output projection
    gemm_nt_kernel<<<dim3(HID / 64, SEQ / 64), 256>>>(AOp, Wo, out, SEQ, HID, HID);
}

// round 2
// speedup vs baseline: 2.0517x; 2.0517x over previous
#include <cuda_runtime.h>
#include <math.h>

// ---------------- problem constants ----------------
#define SEQ     2048
#define HID     4096
#define NH      32
#define NKV     8
#define HD      128
#define KVD     (NKV*HD)     // 1024

// ---------------- scratch (static device globals; no allocation) ----------------
__device__ float g_Xr [SEQ * HID];    // tf32-rounded hidden states
__device__ float g_Wqr[HID * HID];
__device__ float g_Wkr[KVD * HID];
__device__ float g_Wvr[KVD * HID];
__device__ float g_Wor[HID * HID];
__device__ float g_Q  [SEQ * HID];
__device__ float g_K  [SEQ * KVD];
__device__ float g_V  [SEQ * KVD];
__device__ float g_AO [SEQ * HID];    // attention output (tf32-rounded)

__device__ __forceinline__ float tf32r(float x) {
    unsigned r;
    asm("cvt.rna.tf32.f32 %0, %1;" : "=r"(r) : "f"(x));
    return __uint_as_float(r);
}

// ============================================================================
// tf32 rounding prepass (vectorized float4)
// ============================================================================
__global__ void __launch_bounds__(256) round_tf32_kernel(
    const float4* __restrict__ in, float4* __restrict__ out, int n4)
{
    int i = blockIdx.x * blockDim.x + threadIdx.x;
    if (i >= n4) return;
    float4 v = in[i];
    out[i] = make_float4(tf32r(v.x), tf32r(v.y), tf32r(v.z), tf32r(v.w));
}

// ============================================================================
// tf32 tensor-core NT GEMM: C[M,N] = A[M,K] * B[N,K]^T  (row-major, fp32 acc)
// BM=BN=128, BK=32, 256 threads (8 warps), warp tile 32x64 via m16n8k8 mma.
// cp.async double-buffered smem, K-stride padded to 36 (conflict-free frags).
// ============================================================================
#define BM 128
#define BN 128
#define BK 32
#define KP 36

#define GEMM_SMEM_BYTES (2 * (BM + BN) * KP * 4)   // 73728

extern __shared__ float sm_gemm[];

__global__ void __launch_bounds__(256) gemm_tf32_kernel(
    const float* __restrict__ A, const float* __restrict__ B,
    float* __restrict__ C, int M, int N, int K)
{
    const int tid = threadIdx.x;
    const int bm = blockIdx.y * BM;
    const int bn = blockIdx.x * BN;

    float* As = sm_gemm;                    // [2][BM*KP]
    float* Bs = sm_gemm + 2 * BM * KP;      // [2][BN*KP]

    const int warp = tid >> 5, lane = tid & 31;
    const int wm = (warp >> 1) << 5;        // 0,32,64,96
    const int wn = (warp & 1) << 6;         // 0,64
    const int gr = lane >> 2, gc = lane & 3;

    // global->smem load mapping: thread covers rows {lr, lr+32, lr+64, lr+96}, cols lc..lc+3
    const int lr = tid >> 3;                // 0..31
    const int lc = (tid & 7) << 2;          // 0,4,...,28
    const float* Ag = A + (size_t)(bm + lr) * K + lc;
    const float* Bg = B + (size_t)(bn + lr) * K + lc;

    auto load_stage = [&](int kt, int s) {
        float* Ad = As + s * BM * KP;
        float* Bd = Bs + s * BN * KP;
        const size_t koff = (size_t)kt * BK;
#pragma unroll
        for (int it = 0; it < 4; it++) {
            int row = lr + it * 32;
            unsigned da = (unsigned)__cvta_generic_to_shared(Ad + row * KP + lc);
            unsigned db = (unsigned)__cvta_generic_to_shared(Bd + row * KP + lc);
            asm volatile("cp.async.cg.shared.global [%0], [%1], 16;"
                         :: "r"(da), "l"(Ag + (size_t)it * 32 * K + koff));
            asm volatile("cp.async.cg.shared.global [%0], [%1], 16;"
                         :: "r"(db), "l"(Bg + (size_t)it * 32 * K + koff));
        }
        asm volatile("cp.async.commit_group;");
    };

    float acc[2][8][4];
#pragma unroll
    for (int mi = 0; mi < 2; mi++)
#pragma unroll
        for (int nj = 0; nj < 8; nj++)
#pragma unroll
            for (int q = 0; q < 4; q++) acc[mi][nj][q] = 0.f;

    load_stage(0, 0);

    const int nk = K / BK;
    for (int kt = 0; kt < nk; kt++) {
        asm volatile("cp.async.wait_group 0;");
        __syncthreads();
        if (kt + 1 < nk) load_stage(kt + 1, (kt + 1) & 1);

        const unsigned* Au = (const unsigned*)(As + (kt & 1) * BM * KP);
        const unsigned* Bu = (const unsigned*)(Bs + (kt & 1) * BN * KP);

#pragma unroll
        for (int ks = 0; ks < 4; ks++) {
            const int k0 = ks * 8;
            unsigned a[2][4], b[8][2];
#pragma unroll
            for (int mi = 0; mi < 2; mi++) {
                int r = wm + mi * 16 + gr;
                a[mi][0] = Au[r * KP + k0 + gc];
                a[mi][1] = Au[(r + 8) * KP + k0 + gc];
                a[mi][2] = Au[r * KP + k0 + gc + 4];
                a[mi][3] = Au[(r + 8) * KP + k0 + gc + 4];
            }
#pragma unroll
            for (int nj = 0; nj < 8; nj++) {
                int n = wn + nj * 8 + gr;
                b[nj][0] = Bu[n * KP + k0 + gc];
                b[nj][1] = Bu[n * KP + k0 + gc + 4];
            }
#pragma unroll
            for (int mi = 0; mi < 2; mi++)
#pragma unroll
                for (int nj = 0; nj < 8; nj++) {
                    asm volatile(
                        "mma.sync.aligned.m16n8k8.row.col.f32.tf32.tf32.f32 "
                        "{%0,%1,%2,%3}, {%4,%5,%6,%7}, {%8,%9}, {%0,%1,%2,%3};"
                        : "+f"(acc[mi][nj][0]), "+f"(acc[mi][nj][1]),
                          "+f"(acc[mi][nj][2]), "+f"(acc[mi][nj][3])
                        : "r"(a[mi][0]), "r"(a[mi][1]), "r"(a[mi][2]), "r"(a[mi][3]),
                          "r"(b[nj][0]), "r"(b[nj][1]));
                }
        }
        __syncthreads();
    }

    // epilogue
#pragma unroll
    for (int mi = 0; mi < 2; mi++) {
        int r0 = bm + wm + mi * 16 + gr;
#pragma unroll
        for (int nj = 0; nj < 8; nj++) {
            int c = bn + wn + nj * 8 + 2 * gc;
            *(float2*)&C[(size_t)r0 * N + c] = make_float2(acc[mi][nj][0], acc[mi][nj][1]);
            *(float2*)&C[(size_t)(r0 + 8) * N + c] = make_float2(acc[mi][nj][2], acc[mi][nj][3]);
        }
    }
}

// ============================================================================
// RoPE in place on Q and K (unchanged from round 1)
// ============================================================================
#define NQ_PAIRS (SEQ * NH * 64)
#define NK_PAIRS (SEQ * NKV * 64)

__global__ void __launch_bounds__(256) rope_kernel(float* __restrict__ Q, float* __restrict__ K)
{
    int idx = blockIdx.x * blockDim.x + threadIdx.x;
    float* base;
    int s, i;
    if (idx < NQ_PAIRS) {
        s = idx >> 11;
        int p = idx & 2047;
        int h = p >> 6;
        i = p & 63;
        base = Q + (size_t)s * HID + h * HD;
    } else {
        int t = idx - NQ_PAIRS;
        if (t >= NK_PAIRS) return;
        s = t >> 9;
        int p = t & 511;
        int h = p >> 6;
        i = p & 63;
        base = K + (size_t)s * KVD + h * HD;
    }
    double invf_d = exp(-(double)i * (13.122363377404328 / 64.0));
    float freq = (float)s * (float)invf_d;
    float c = cosf(freq);
    float sn = sinf(freq);
    float x1 = base[i];
    float x2 = base[i + 64];
    base[i]      = x1 * c - x2 * sn;
    base[i + 64] = x2 * c + x1 * sn;
}

// ============================================================================
// Flash attention fp32 (round 1 kernel) + tf32 rounding on output
// ============================================================================
#define QSTR 132
#define SSTR 65
#define ATTN_SMEM_FLOATS (3*64*QSTR + 64*SSTR + 64*3 + 256)
#define ATTN_SMEM_BYTES  (ATTN_SMEM_FLOATS * 4)

extern __shared__ float sm_attn[];

__global__ void __launch_bounds__(256) attn_kernel(
    const float* __restrict__ Q, const float* __restrict__ K,
    const float* __restrict__ V, float* __restrict__ O)
{
    float* sQ = sm_attn;
    float* sK = sQ + 64 * QSTR;
    float* sV = sK + 64 * QSTR;
    float* sS = sV + 64 * QSTR;
    float* sM = sS + 64 * SSTR;
    float* sL = sM + 64;
    float* sA = sL + 64;
    float* sR = sA + 64;

    const int tid = threadIdx.x;
    const int qt = blockIdx.x;
    const int h  = blockIdx.y;
    const int hk = h >> 2;

    const int ty = tid >> 4, tx = tid & 15;
    const int ry = ty * 4;
    const int cx4 = tx * 4;
    const int cx8 = tx * 8;

    for (int v = tid; v < 64 * 32; v += 256) {
        int row = v >> 5, c4 = (v & 31) << 2;
        *(float4*)&sQ[row * QSTR + c4] =
            *(const float4*)&Q[(size_t)(qt * 64 + row) * HID + h * HD + c4];
    }
    if (tid < 64) { sM[tid] = -1e30f; sL[tid] = 0.f; }

    float acc[4][8];
#pragma unroll
    for (int i = 0; i < 4; i++)
#pragma unroll
        for (int j = 0; j < 8; j++) acc[i][j] = 0.f;

    __syncthreads();

    const float scale = 0.08838834764831845f;
    const int r  = tid & 63;
    const int qd = tid >> 6;

    for (int kt = 0; kt <= qt; kt++) {
        for (int v = tid; v < 64 * 32; v += 256) {
            int row = v >> 5, c4 = (v & 31) << 2;
            size_t gb = (size_t)(kt * 64 + row) * KVD + hk * HD + c4;
            *(float4*)&sK[row * QSTR + c4] = *(const float4*)&K[gb];
            *(float4*)&sV[row * QSTR + c4] = *(const float4*)&V[gb];
        }
        __syncthreads();

        float s[4][4];
#pragma unroll
        for (int i = 0; i < 4; i++)
#pragma unroll
            for (int j = 0; j < 4; j++) s[i][j] = 0.f;

        for (int d4 = 0; d4 < 128; d4 += 4) {
            float4 q0 = *(const float4*)&sQ[(ry + 0) * QSTR + d4];
            float4 q1 = *(const float4*)&sQ[(ry + 1) * QSTR + d4];
            float4 q2 = *(const float4*)&sQ[(ry + 2) * QSTR + d4];
            float4 q3 = *(const float4*)&sQ[(ry + 3) * QSTR + d4];
            float4 k0 = *(const float4*)&sK[(cx4 + 0) * QSTR + d4];
            float4 k1 = *(const float4*)&sK[(cx4 + 1) * QSTR + d4];
            float4 k2 = *(const float4*)&sK[(cx4 + 2) * QSTR + d4];
            float4 k3 = *(const float4*)&sK[(cx4 + 3) * QSTR + d4];
#define DOT4(a,b) (a.x*b.x + a.y*b.y + a.z*b.z + a.w*b.w)
            s[0][0] += DOT4(q0,k0); s[0][1] += DOT4(q0,k1); s[0][2] += DOT4(q0,k2); s[0][3] += DOT4(q0,k3);
            s[1][0] += DOT4(q1,k0); s[1][1] += DOT4(q1,k1); s[1][2] += DOT4(q1,k2); s[1][3] += DOT4(q1,k3);
            s[2][0] += DOT4(q2,k0); s[2][1] += DOT4(q2,k1); s[2][2] += DOT4(q2,k2); s[2][3] += DOT4(q2,k3);
            s[3][0] += DOT4(q3,k0); s[3][1] += DOT4(q3,k1); s[3][2] += DOT4(q3,k2); s[3][3] += DOT4(q3,k3);
#undef DOT4
        }

        const bool diag = (kt == qt);
#pragma unroll
        for (int i = 0; i < 4; i++) {
            int gq = qt * 64 + ry + i;
#pragma unroll
            for (int j = 0; j < 4; j++) {
                float val = s[i][j] * scale;
                if (diag && (kt * 64 + cx4 + j > gq)) val = -1e30f;
                sS[(ry + i) * SSTR + cx4 + j] = val;
            }
        }
        __syncthreads();

        {
            float mx = -1e30f;
            const float* rowp = &sS[r * SSTR + qd * 16];
#pragma unroll
            for (int j = 0; j < 16; j++) mx = fmaxf(mx, rowp[j]);
            sR[qd * 64 + r] = mx;
        }
        __syncthreads();
        if (tid < 64) {
            float mold = sM[tid];
            float mnew = fmaxf(fmaxf(sR[tid], sR[64 + tid]),
                               fmaxf(sR[128 + tid], sR[192 + tid]));
            mnew = fmaxf(mold, mnew);
            sM[tid] = mnew;
            sA[tid] = expf(mold - mnew);
        }
        __syncthreads();

        {
            float mnew = sM[r];
            float psum = 0.f;
            float* rowp = &sS[r * SSTR + qd * 16];
#pragma unroll
            for (int j = 0; j < 16; j++) {
                float p = expf(rowp[j] - mnew);
                rowp[j] = p;
                psum += p;
            }
            sR[qd * 64 + r] = psum;
        }
#pragma unroll
        for (int i = 0; i < 4; i++) {
            float al = sA[ry + i];
#pragma unroll
            for (int j = 0; j < 8; j++) acc[i][j] *= al;
        }
        __syncthreads();
        if (tid < 64) {
            sL[tid] = sL[tid] * sA[tid] +
                      (sR[tid] + sR[64 + tid]) + (sR[128 + tid] + sR[192 + tid]);
        }

        for (int kk = 0; kk < 64; kk++) {
            float4 va = *(const float4*)&sV[kk * QSTR + cx8];
            float4 vb = *(const float4*)&sV[kk * QSTR + cx8 + 4];
#pragma unroll
            for (int i = 0; i < 4; i++) {
                float p = sS[(ry + i) * SSTR + kk];
                acc[i][0] += p * va.x; acc[i][1] += p * va.y;
                acc[i][2] += p * va.z; acc[i][3] += p * va.w;
                acc[i][4] += p * vb.x; acc[i][5] += p * vb.y;
                acc[i][6] += p * vb.z; acc[i][7] += p * vb.w;
            }
        }
        __syncthreads();
    }

    // finalize; round to tf32 so the Wo GEMM sees pre-rounded operands
#pragma unroll
    for (int i = 0; i < 4; i++) {
        float inv = 1.0f / sL[ry + i];
        size_t gb = (size_t)(qt * 64 + ry + i) * HID + h * HD + cx8;
        float4 oa = make_float4(tf32r(acc[i][0] * inv), tf32r(acc[i][1] * inv),
                                tf32r(acc[i][2] * inv), tf32r(acc[i][3] * inv));
        float4 ob = make_float4(tf32r(acc[i][4] * inv), tf32r(acc[i][5] * inv),
                                tf32r(acc[i][6] * inv), tf32r(acc[i][7] * inv));
        *(float4*)&O[gb] = oa;
        *(float4*)&O[gb + 4] = ob;
    }
}

// ============================================================================
// launch
// ============================================================================
extern "C" void kernel_launch(void* const* d_in, const int* in_sizes, int n_in,
                              void* d_out, int out_size)
{
    const float* X  = (const float*)d_in[0];
    const float* Wq = (const float*)d_in[1];
    const float* Wk = (const float*)d_in[2];
    const float* Wv = (const float*)d_in[3];
    const float* Wo = (const float*)d_in[4];
    float* out = (float*)d_out;

    float *Xr, *Wqr, *Wkr, *Wvr, *Wor, *Qp, *Kp, *Vp, *AOp;
    cudaGetSymbolAddress((void**)&Xr,  g_Xr);
    cudaGetSymbolAddress((void**)&Wqr, g_Wqr);
    cudaGetSymbolAddress((void**)&Wkr, g_Wkr);
    cudaGetSymbolAddress((void**)&Wvr, g_Wvr);
    cudaGetSymbolAddress((void**)&Wor, g_Wor);
    cudaGetSymbolAddress((void**)&Qp,  g_Q);
    cudaGetSymbolAddress((void**)&Kp,  g_K);
    cudaGetSymbolAddress((void**)&Vp,  g_V);
    cudaGetSymbolAddress((void**)&AOp, g_AO);

    cudaFuncSetAttribute(gemm_tf32_kernel,
                         cudaFuncAttributeMaxDynamicSharedMemorySize,
                         GEMM_SMEM_BYTES);
    cudaFuncSetAttribute(attn_kernel,
                         cudaFuncAttributeMaxDynamicSharedMemorySize,
                         ATTN_SMEM_BYTES);

    // ---- tf32 rounding prepass ----
    {
        int n4;
        n4 = SEQ * HID / 4;
        round_tf32_kernel<<<(n4 + 255) / 256, 256>>>((const float4*)X,  (float4*)Xr,  n4);
        n4 = HID * HID / 4;
        round_tf32_kernel<<<(n4 + 255) / 256, 256>>>((const float4*)Wq, (float4*)Wqr, n4);
        n4 = KVD * HID / 4;
        round_tf32_kernel<<<(n4 + 255) / 256, 256>>>((const float4*)Wk, (float4*)Wkr, n4);
        round_tf32_kernel<<<(n4 + 255) / 256, 256>>>((const float4*)Wv, (float4*)Wvr, n4);
        n4 = HID * HID / 4;
        round_tf32_kernel<<<(n4 + 255) / 256, 256>>>((const float4*)Wo, (float4*)Wor, n4);
    }

    // ---- QKV projections (tensor-core tf32) ----
    gemm_tf32_kernel<<<dim3(HID / BN, SEQ / BM), 256, GEMM_SMEM_BYTES>>>(Xr, Wqr, Qp, SEQ, HID, HID);
    gemm_tf32_kernel<<<dim3(KVD / BN, SEQ / BM), 256, GEMM_SMEM_BYTES>>>(Xr, Wkr, Kp, SEQ, KVD, HID);
    gemm_tf32_kernel<<<dim3(KVD / BN, SEQ / BM), 256, GEMM_SMEM_BYTES>>>(Xr, Wvr, Vp, SEQ, KVD, HID);

    // ---- RoPE ----
    {
        int total = NQ_PAIRS + NK_PAIRS;
        rope_kernel<<<(total + 255) / 256, 256>>>(Qp, Kp);
    }

    // ---- attention (fp32) ----
    attn_kernel<<<dim3(SEQ / 64, NH), 256, ATTN_SMEM_BYTES>>>(Qp, Kp, Vp, AOp);

    // ---- output projection ----
    gemm_tf32_kernel<<<dim3(HID / BN, SEQ / BM), 256, GEMM_SMEM_BYTES>>>(AOp, Wor, out, SEQ, HID, HID);
}